// round 13
// baseline (speedup 1.0000x reference)
#include <cuda_runtime.h>
#include <cstdint>
#include <math_constants.h>

#define NROWS   131072
#define DDIM    64
#define ECODES  1024
#define BLOCK   256
#define RPB     128
#define GRID_A  (NROWS / RPB)      // 1024
#define NTILES  (ECODES / 8)       // 128 code tiles of 8

__device__ float        g_loss_acc;          // zero-init; reset by last CTA of vq_out
__device__ unsigned int g_ctr;               // zero-init; wraps to 0
__device__ float        g_t2[ECODES];        // exact fp32 ||w_c||^2 (sequential chain)
__device__ float        g_wpack[ECODES * DDIM];  // tf32-valued, mma-fragment-packed
__device__ int          g_idx[NROWS];
__device__ int          g_fall[NROWS];
__device__ int          g_nfall;             // reset by prep each call

// ---- prep: t2 exact, w packed as tf32 B-fragments, reset fallback counter ----
// pack layout: code c = ct*8+g; slot (ct*32 + g*4 + q)*16 holds, for kb=0..7:
//   [kb*2+0] = tf32(w[c][kb*8+q]), [kb*2+1] = tf32(w[c][kb*8+q+4])
__global__ __launch_bounds__(256) void vq_prep(const float* __restrict__ wt) {
    int c = blockIdx.x * blockDim.x + threadIdx.x;
    if (c == 0) g_nfall = 0;
    if (c < ECODES) {
        const float* wr = wt + c * DDIM;
        float v[DDIM];
        float s = 0.0f;
        #pragma unroll
        for (int k = 0; k < DDIM; k++) {
            v[k] = wr[k];
            s = __fadd_rn(s, __fmul_rn(v[k], v[k]));
        }
        g_t2[c] = s;
        int ct = c >> 3, g = c & 7;
        #pragma unroll
        for (int q = 0; q < 4; q++) {
            int base = (ct * 32 + g * 4 + q) * 16;
            #pragma unroll
            for (int kb = 0; kb < 8; kb++) {
                unsigned u0, u1;
                asm("cvt.rna.tf32.f32 %0, %1;" : "=r"(u0) : "f"(v[kb * 8 + q]));
                asm("cvt.rna.tf32.f32 %0, %1;" : "=r"(u1) : "f"(v[kb * 8 + q + 4]));
                g_wpack[base + kb * 2]     = __uint_as_float(u0);
                g_wpack[base + kb * 2 + 1] = __uint_as_float(u1);
            }
        }
    }
}

__device__ __forceinline__ void mma_tf32(float& c0, float& c1, float& c2, float& c3,
                                         unsigned a0, unsigned a1, unsigned a2, unsigned a3,
                                         unsigned b0, unsigned b1) {
    asm volatile(
        "mma.sync.aligned.m16n8k8.row.col.f32.tf32.tf32.f32 "
        "{%0,%1,%2,%3}, {%4,%5,%6,%7}, {%8,%9}, {%0,%1,%2,%3};"
        : "+f"(c0), "+f"(c1), "+f"(c2), "+f"(c3)
        : "r"(a0), "r"(a1), "r"(a2), "r"(a3), "r"(b0), "r"(b1));
}

// ---- phase A: tf32 prefilter + margin certificate + enc zero ----
__global__ __launch_bounds__(BLOCK) void vq_filter(
    const float* __restrict__ inp, float* out_enc)
{
    __shared__ float xs[RPB * 66];     // x tile, stride 66 to spread banks
    __shared__ float t2s[ECODES];
    __shared__ float thr_s;
    __shared__ float wmax_s[8];

    const int tid  = threadIdx.x;
    const int lane = tid & 31;
    const int warp = tid >> 5;        // 8 warps -> 8 row-tiles of 16
    const int g    = lane >> 2;       // 0..7
    const int q    = lane & 3;        // 0..3
    const size_t rowbase = (size_t)blockIdx.x * RPB;

    // stage x (coalesced) and t2
    {
        const float* gx = inp + rowbase * DDIM;
        for (int i = tid; i < RPB * DDIM; i += BLOCK)
            xs[(i >> 6) * 66 + (i & 63)] = gx[i];
        float m = 0.0f;
        #pragma unroll
        for (int j = 0; j < 4; j++) {
            float t = g_t2[tid + j * BLOCK];
            t2s[tid + j * BLOCK] = t;
            m = fmaxf(m, t);
        }
        #pragma unroll
        for (int off = 16; off > 0; off >>= 1)
            m = fmaxf(m, __shfl_xor_sync(0xffffffffu, m, off));
        if (lane == 0) wmax_s[warp] = m;
    }
    __syncthreads();
    if (tid == 0) {
        float m = wmax_s[0];
        #pragma unroll
        for (int j = 1; j < 8; j++) m = fmaxf(m, wmax_s[j]);
        float wn = sqrtf(m);
        // |approx-exact| per dist <= 2*(2^-10 * ||x|| * ||w||max) + slop; ||x||<=12
        float e_dist = 2.0f * (9.765625e-4f * 12.0f * wn) + 4e-5f;
        thr_s = 2.6f * e_dist;         // 2*e_dist with 1.3x safety
    }

    // zero encodings (overlaps with mma below; alignment-safe)
    if (out_enc) {
        float* ebase = out_enc + rowbase * (size_t)ECODES;
        const int total = RPB * ECODES;
        const int head = (int)(((16u - ((uintptr_t)ebase & 15u)) & 15u) >> 2);
        if (tid < head) ebase[tid] = 0.0f;
        float4* v = reinterpret_cast<float4*>(ebase + head);
        const int nvec = (total - head) >> 2;
        float4 z = make_float4(0.f, 0.f, 0.f, 0.f);
        for (int i = tid; i < nvec; i += BLOCK) v[i] = z;
        const int tail_start = head + (nvec << 2);
        if (tid < total - tail_start) ebase[tail_start + tid] = 0.0f;
    }
    __syncthreads();

    // A fragments for this warp's 16 rows (rows rt*16+g and +8), tf32-converted once
    const int r0 = warp * 16 + g;
    unsigned a[8][4];
    #pragma unroll
    for (int kb = 0; kb < 8; kb++) {
        float f0 = xs[r0 * 66 + kb * 8 + q];
        float f1 = xs[(r0 + 8) * 66 + kb * 8 + q];
        float f2 = xs[r0 * 66 + kb * 8 + q + 4];
        float f3 = xs[(r0 + 8) * 66 + kb * 8 + q + 4];
        asm("cvt.rna.tf32.f32 %0, %1;" : "=r"(a[kb][0]) : "f"(f0));
        asm("cvt.rna.tf32.f32 %0, %1;" : "=r"(a[kb][1]) : "f"(f1));
        asm("cvt.rna.tf32.f32 %0, %1;" : "=r"(a[kb][2]) : "f"(f2));
        asm("cvt.rna.tf32.f32 %0, %1;" : "=r"(a[kb][3]) : "f"(f3));
    }

    float m1[2] = {CUDART_INF_F, CUDART_INF_F};
    float m2[2] = {CUDART_INF_F, CUDART_INF_F};
    int   i1[2] = {0, 0};

    #pragma unroll 1
    for (int ct = 0; ct < NTILES; ct++) {
        const float4* wp = reinterpret_cast<const float4*>(g_wpack) + (ct * 32 + lane) * 4;
        float4 w0 = wp[0], w1 = wp[1], w2 = wp[2], w3 = wp[3];
        float c0 = 0.f, c1 = 0.f, c2 = 0.f, c3 = 0.f;
        mma_tf32(c0,c1,c2,c3, a[0][0],a[0][1],a[0][2],a[0][3], __float_as_uint(w0.x), __float_as_uint(w0.y));
        mma_tf32(c0,c1,c2,c3, a[1][0],a[1][1],a[1][2],a[1][3], __float_as_uint(w0.z), __float_as_uint(w0.w));
        mma_tf32(c0,c1,c2,c3, a[2][0],a[2][1],a[2][2],a[2][3], __float_as_uint(w1.x), __float_as_uint(w1.y));
        mma_tf32(c0,c1,c2,c3, a[3][0],a[3][1],a[3][2],a[3][3], __float_as_uint(w1.z), __float_as_uint(w1.w));
        mma_tf32(c0,c1,c2,c3, a[4][0],a[4][1],a[4][2],a[4][3], __float_as_uint(w2.x), __float_as_uint(w2.y));
        mma_tf32(c0,c1,c2,c3, a[5][0],a[5][1],a[5][2],a[5][3], __float_as_uint(w2.z), __float_as_uint(w2.w));
        mma_tf32(c0,c1,c2,c3, a[6][0],a[6][1],a[6][2],a[6][3], __float_as_uint(w3.x), __float_as_uint(w3.y));
        mma_tf32(c0,c1,c2,c3, a[7][0],a[7][1],a[7][2],a[7][3], __float_as_uint(w3.z), __float_as_uint(w3.w));

        // acc layout: c0=(row g, col 2q), c1=(row g, col 2q+1), c2=(+8, 2q), c3=(+8, 2q+1)
        const int cA = ct * 8 + 2 * q;
        float t2a = t2s[cA], t2b = t2s[cA + 1];
        float d;
        d = __fmaf_rn(c0, -2.0f, t2a);
        if (d < m1[0]) { m2[0] = m1[0]; m1[0] = d; i1[0] = cA; } else m2[0] = fminf(m2[0], d);
        d = __fmaf_rn(c1, -2.0f, t2b);
        if (d < m1[0]) { m2[0] = m1[0]; m1[0] = d; i1[0] = cA + 1; } else m2[0] = fminf(m2[0], d);
        d = __fmaf_rn(c2, -2.0f, t2a);
        if (d < m1[1]) { m2[1] = m1[1]; m1[1] = d; i1[1] = cA; } else m2[1] = fminf(m2[1], d);
        d = __fmaf_rn(c3, -2.0f, t2b);
        if (d < m1[1]) { m2[1] = m1[1]; m1[1] = d; i1[1] = cA + 1; } else m2[1] = fminf(m2[1], d);
    }

    // merge across the 4 lanes of each row group (xor 1, 2)
    #pragma unroll
    for (int r = 0; r < 2; r++) {
        float a1 = m1[r]; int ai = i1[r]; float a2 = m2[r];
        #pragma unroll
        for (int off = 1; off <= 2; off <<= 1) {
            float o1 = __shfl_xor_sync(0xffffffffu, a1, off);
            int   oi = __shfl_xor_sync(0xffffffffu, ai, off);
            float o2 = __shfl_xor_sync(0xffffffffu, a2, off);
            float hi = fmaxf(a1, o1);
            if (o1 < a1) { a1 = o1; ai = oi; }
            a2 = fminf(fminf(a2, o2), hi);
        }
        if (q == 0) {
            int grow = (int)rowbase + warp * 16 + g + r * 8;
            g_idx[grow] = ai;
            if (!(a2 - a1 > thr_s)) {             // margin fails -> exact rescan
                int p = atomicAdd(&g_nfall, 1);
                g_fall[p] = grow;
            }
        }
    }
}

// ---- phase B: exact rescan (bit-exact reference replication) for flagged rows ----
__global__ __launch_bounds__(256) void vq_exact(
    const float* __restrict__ inp, const float* __restrict__ wt)
{
    const int wgid = (blockIdx.x * blockDim.x + threadIdx.x) >> 5;
    const int lane = threadIdx.x & 31;
    const int nw = (gridDim.x * blockDim.x) >> 5;
    const int n = *((volatile int*)&g_nfall);

    for (int i = wgid; i < n; i += nw) {
        const int row = g_fall[i];
        const float* xr = inp + (size_t)row * DDIM;
        float x[DDIM];
        #pragma unroll
        for (int k4 = 0; k4 < 16; k4++) {
            float4 v = reinterpret_cast<const float4*>(xr)[k4];
            x[4*k4] = v.x; x[4*k4+1] = v.y; x[4*k4+2] = v.z; x[4*k4+3] = v.w;
        }
        float t1 = 0.0f;
        #pragma unroll
        for (int k = 0; k < DDIM; k++)
            t1 = __fadd_rn(t1, __fmul_rn(x[k], x[k]));

        float best = CUDART_INF_F; int bi = 0;
        #pragma unroll 1
        for (int j = 0; j < 32; j++) {
            int c = lane + 32 * j;                 // ascending within thread
            const float* wr = wt + (size_t)c * DDIM;
            float dacc = 0.0f;
            #pragma unroll
            for (int k = 0; k < DDIM; k++)
                dacc = __fmaf_rn(x[k], wr[k], dacc);
            float u = __fadd_rn(t1, g_t2[c]);
            float dist = __fsub_rn(u, __fmul_rn(2.0f, dacc));
            if (dist < best) { best = dist; bi = c; }
        }
        #pragma unroll
        for (int off = 1; off < 32; off <<= 1) {
            float ob = __shfl_xor_sync(0xffffffffu, best, off);
            int   oi = __shfl_xor_sync(0xffffffffu, bi, off);
            if (ob < best || (ob == best && oi < bi)) { best = ob; bi = oi; }
        }
        if (lane == 0) g_idx[row] = bi;
    }
}

// ---- phase C: scatter ones + quantized + loss ----
__global__ __launch_bounds__(BLOCK) void vq_out(
    const float* __restrict__ inp, const float* __restrict__ wt,
    float* out_q, float* out_enc, float* out_loss)
{
    __shared__ int   idx_sh[RPB];
    __shared__ float red[BLOCK];
    const int tid = threadIdx.x;
    const size_t rowbase = (size_t)blockIdx.x * RPB;

    if (tid < RPB) idx_sh[tid] = g_idx[rowbase + tid];
    __syncthreads();

    if (out_enc && tid < RPB)
        out_enc[(rowbase + tid) * (size_t)ECODES + (size_t)idx_sh[tid]] = 1.0f;

    float part = 0.0f;
    for (int i = tid; i < RPB * DDIM; i += BLOCK) {
        int r = i >> 6, k = i & 63;
        float qv = wt[(size_t)idx_sh[r] * DDIM + k];
        float xv = inp[(rowbase + r) * DDIM + k];
        float dqx = __fsub_rn(qv, xv);
        part = __fadd_rn(part, __fmul_rn(dqx, dqx));
        if (out_q)
            out_q[rowbase * DDIM + i] = __fadd_rn(xv, dqx);
    }
    red[tid] = part;
    __syncthreads();
    for (int s = BLOCK / 2; s > 0; s >>= 1) {
        if (tid < s) red[tid] += red[tid + s];
        __syncthreads();
    }
    if (tid == 0) {
        atomicAdd(&g_loss_acc, red[0]);
        __threadfence();
        unsigned int done = atomicAdd(&g_ctr, 1u);
        if (done == GRID_A - 1) {
            float m = *((volatile float*)&g_loss_acc) / 8388608.0f;
            if (out_loss) out_loss[0] = __fadd_rn(m, __fmul_rn(0.25f, m));
            g_loss_acc = 0.0f;
            __threadfence();
            g_ctr = 0u;
        }
    }
}

extern "C" void kernel_launch(void* const* d_in, const int* in_sizes, int n_in,
                              void* d_out, int out_size)
{
    const float* inp = nullptr;
    const float* wt  = nullptr;
    for (int i = 0; i < n_in; i++) {
        if (in_sizes[i] == 8388608) inp = (const float*)d_in[i];
        else if (in_sizes[i] == 65536) wt = (const float*)d_in[i];
    }
    if (!inp || !wt) return;

    float* out = (float*)d_out;
    const long long Q = 8388608LL, ENC = 134217728LL;
    long long os = (long long)out_size;

    float* oL = nullptr; float* oQ = nullptr; float* oE = nullptr;
    if (os == 1 + Q + ENC)      { oL = out; oQ = out + 1; oE = out + 1 + Q; }
    else if (os == Q + ENC)     { oQ = out; oE = out + Q; }
    else if (os == ENC)         { oE = out; }
    else if (os == Q)           { oQ = out; }
    else if (os == 1)           { oL = out; }
    else {
        oL = out;
        if (os >= 1 + Q) oQ = out + 1;
        if (os >= 1 + Q + ENC) oE = out + 1 + Q;
    }

    vq_prep<<<4, 256>>>(wt);
    vq_filter<<<GRID_A, BLOCK>>>(inp, oE);
    vq_exact<<<512, 256>>>(inp, wt);
    vq_out<<<GRID_A, BLOCK>>>(inp, wt, oQ, oE, oL);
}

// round 14
// speedup vs baseline: 10.3212x; 10.3212x over previous
#include <cuda_runtime.h>
#include <cstdint>
#include <math_constants.h>

// Problem constants
#define NROWS   131072      // 256*512
#define DDIM    64
#define ECODES  1024
#define CHUNK   128         // codes staged per iteration
#define NCHUNK  (ECODES / CHUNK)
#define BLOCK   256
#define RPB     128         // rows per CTA
#define GRID    (NROWS / RPB)

// smem layout sizes (R6-champion layout + t1 array)
#define XD_STRIDE 65                    // ULL per row (64 data + 1 pad)
#define XD_ULL    (RPB * XD_STRIDE)     // 8320 ULL = 66560 B
#define W_KSTRIDE 162                   // floats per k row (16 groups * 10 + 2)
#define W_FLOATS  (DDIM * W_KSTRIDE)    // 10368 floats = 41472 B
#define OFF_W     (XD_ULL * 8)
#define OFF_T2    (OFF_W + W_FLOATS * 4)
#define OFF_T1    (OFF_T2 + CHUNK * 4)
#define OFF_IDX   (OFF_T1 + RPB * 4)
#define OFF_RED   (OFF_IDX + RPB * 4)
#define SMEM_BYTES (OFF_RED + BLOCK * 4)

typedef unsigned long long ull;

__device__ float        g_loss_acc;   // zero-init; reset to 0 by final CTA each call
__device__ unsigned int g_ctr;        // zero-init; wraps back to 0 each call
__device__ float        g_t2[ECODES];

__device__ __forceinline__ ull f32x2_pack(float a, float b) {
    ull r; asm("mov.b64 %0, {%1, %2};" : "=l"(r) : "f"(a), "f"(b)); return r;
}
__device__ __forceinline__ void f32x2_unpack(ull v, float& a, float& b) {
    asm("mov.b64 {%0, %1}, %2;" : "=f"(a), "=f"(b) : "l"(v));
}
__device__ __forceinline__ ull f32x2_fma(ull a, ull b, ull c) {
    ull r; asm("fma.rn.f32x2 %0, %1, %2, %3;" : "=l"(r) : "l"(a), "l"(b), "l"(c)); return r;
}

// ---- prep: t2[c] = sum_k fl(w[c][k]^2), sequential adds ----
__global__ __launch_bounds__(256) void vq_prep_kernel(const float* __restrict__ wt) {
    int c = blockIdx.x * blockDim.x + threadIdx.x;
    if (c < ECODES) {
        const float* wr = wt + (size_t)c * DDIM;
        float s = 0.0f;
        #pragma unroll
        for (int k = 0; k < DDIM; k++)
            s = __fadd_rn(s, __fmul_rn(wr[k], wr[k]));
        g_t2[c] = s;
    }
}

// ---- main: R6-champion hot loop + early enc-zero + fused loss finalize ----
__global__ __launch_bounds__(BLOCK, 2) void vq_main_kernel(
    const float* __restrict__ inp,   // [131072, 64]
    const float* __restrict__ wt,    // [1024, 64]
    float* out_q,                    // [131072, 64] or null
    float* out_enc,                  // [131072, 1024] or null (only 4B-aligned)
    float* out_loss)                 // [1] or null
{
    extern __shared__ __align__(16) char smem_raw[];
    ull*   xdup  = reinterpret_cast<ull*>(smem_raw);                  // [128][65] (x,x)
    float* wsh   = reinterpret_cast<float*>(smem_raw + OFF_W);        // [64][162] grouped codes
    float* t2sh  = reinterpret_cast<float*>(smem_raw + OFF_T2);       // [128]
    float* t1sh  = reinterpret_cast<float*>(smem_raw + OFF_T1);       // [128]
    int*   idx_sh= reinterpret_cast<int*>(smem_raw + OFF_IDX);        // [128]
    float* red   = reinterpret_cast<float*>(smem_raw + OFF_RED);      // [256]

    const int tid = threadIdx.x;
    const int rg  = tid >> 4;        // 0..15 : row group (8 rows)
    const int cg  = tid & 15;        // 0..15 : code group (8 codes per chunk)
    const size_t rowbase = (size_t)blockIdx.x * RPB;

    // ---- stage x duplicated as (x,x) pairs; coalesced gmem read ----
    {
        const float* gx = inp + rowbase * DDIM;
        for (int i = tid; i < RPB * DDIM; i += BLOCK) {
            float v = gx[i];
            xdup[(i >> 6) * XD_STRIDE + (i & 63)] = f32x2_pack(v, v);
        }
    }

    // ---- early encodings zero-fill: stores drain while we compute below ----
    // (out_enc may be only 4B-aligned: peel to 16B, vector body, scalar tail)
    if (out_enc) {
        float* ebase = out_enc + rowbase * (size_t)ECODES;
        const int total = RPB * ECODES;
        const int head = (int)(((16u - ((uintptr_t)ebase & 15u)) & 15u) >> 2);
        if (tid < head) ebase[tid] = 0.0f;
        float4* v = reinterpret_cast<float4*>(ebase + head);
        const int nvec = (total - head) >> 2;
        float4 z = make_float4(0.f, 0.f, 0.f, 0.f);
        for (int i = tid; i < nvec; i += BLOCK) v[i] = z;
        const int tail_start = head + (nvec << 2);
        if (tid < total - tail_start) ebase[tail_start + tid] = 0.0f;
    }
    __syncthreads();

    // ---- t1 per row into smem: sequential fl(x^2) adds, k ascending ----
    if (tid < RPB) {
        const float* xr = reinterpret_cast<const float*>(xdup + tid * XD_STRIDE);
        float s = 0.0f;
        #pragma unroll
        for (int k = 0; k < DDIM; k++) {
            float xv = xr[2 * k];                 // low lane of (x,x)
            s = __fadd_rn(s, __fmul_rn(xv, xv));
        }
        t1sh[tid] = s;
    }

    float best[8]; int bidx[8];
    #pragma unroll
    for (int r = 0; r < 8; r++) { best[r] = CUDART_INF_F; bidx[r] = 0; }

    for (int ch = 0; ch < NCHUNK; ch++) {
        __syncthreads();
        // stage weight chunk: code c -> wsh[k*162 + (c>>3)*10 + (c&7)]
        {
            const float* wg = wt + (size_t)ch * CHUNK * DDIM;
            for (int i = tid; i < CHUNK * DDIM; i += BLOCK) {
                int c = i >> 6, k = i & 63;
                wsh[k * W_KSTRIDE + (c >> 3) * 10 + (c & 7)] = wg[i];
            }
            if (tid < CHUNK) t2sh[tid] = g_t2[ch * CHUNK + tid];
        }
        __syncthreads();

        ull acc[8][4];
        #pragma unroll
        for (int r = 0; r < 8; r++)
            #pragma unroll
            for (int p = 0; p < 4; p++) acc[r][p] = 0ull;

        const ull* xbase = xdup + rg * 8 * XD_STRIDE;
        #pragma unroll 2
        for (int k = 0; k < DDIM; k++) {
            ull wv[4];
            const ull* wrow = reinterpret_cast<const ull*>(wsh + k * W_KSTRIDE + cg * 10);
            #pragma unroll
            for (int p = 0; p < 4; p++) wv[p] = wrow[p];
            ull xr[8];
            #pragma unroll
            for (int r = 0; r < 8; r++) xr[r] = xbase[r * XD_STRIDE + k];
            #pragma unroll
            for (int r = 0; r < 8; r++)
                #pragma unroll
                for (int p = 0; p < 4; p++)
                    acc[r][p] = f32x2_fma(xr[r], wv[p], acc[r][p]);
        }

        // epilogue: distances + running argmin (codes ascend; strict '<' => first idx)
        const int cbase = ch * CHUNK + cg * 8;
        #pragma unroll
        for (int r = 0; r < 8; r++) {
            float t1v = t1sh[rg * 8 + r];
            float b = best[r]; int bi = bidx[r];
            #pragma unroll
            for (int p = 0; p < 4; p++) {
                float d0, d1; f32x2_unpack(acc[r][p], d0, d1);
                float u0 = __fadd_rn(t1v, t2sh[cg * 8 + 2 * p]);
                float dist0 = __fsub_rn(u0, __fmul_rn(2.0f, d0));
                if (dist0 < b) { b = dist0; bi = cbase + 2 * p; }
                float u1 = __fadd_rn(t1v, t2sh[cg * 8 + 2 * p + 1]);
                float dist1 = __fsub_rn(u1, __fmul_rn(2.0f, d1));
                if (dist1 < b) { b = dist1; bi = cbase + 2 * p + 1; }
            }
            best[r] = b; bidx[r] = bi;
        }
    }

    // ---- cross-thread argmin over the 16 code-groups (width-16 shuffle) ----
    #pragma unroll
    for (int r = 0; r < 8; r++) {
        float d = best[r]; int ix = bidx[r];
        #pragma unroll
        for (int off = 1; off < 16; off <<= 1) {
            float d2 = __shfl_xor_sync(0xffffffffu, d, off, 16);
            int   i2 = __shfl_xor_sync(0xffffffffu, ix, off, 16);
            if (d2 < d || (d2 == d && i2 < ix)) { d = d2; ix = i2; }
        }
        if (cg == 0) idx_sh[rg * 8 + r] = ix;
    }
    __syncthreads();   // idx_sh visible; enc zeros long since retired (same-CTA order via this barrier)

    if (out_enc && tid < RPB)
        out_enc[(rowbase + tid) * (size_t)ECODES + (size_t)idx_sh[tid]] = 1.0f;

    // ---- quantized_st + loss partial ----
    float part = 0.0f;
    for (int i = tid; i < RPB * DDIM; i += BLOCK) {
        int r = i >> 6, k = i & 63;
        float q  = wt[(size_t)idx_sh[r] * DDIM + k];
        float xv = inp[(rowbase + r) * DDIM + k];
        float dqx = __fsub_rn(q, xv);
        part = __fadd_rn(part, __fmul_rn(dqx, dqx));
        if (out_q)
            out_q[rowbase * DDIM + i] = __fadd_rn(xv, dqx);
    }
    red[tid] = part;
    __syncthreads();
    for (int s = BLOCK / 2; s > 0; s >>= 1) {
        if (tid < s) red[tid] += red[tid + s];
        __syncthreads();
    }

    // ---- loss accumulate + last-CTA finalize ----
    if (tid == 0) {
        atomicAdd(&g_loss_acc, red[0]);
        __threadfence();
        unsigned int done = atomicAdd(&g_ctr, 1u);
        if (done == GRID - 1) {
            float m = *((volatile float*)&g_loss_acc) / 8388608.0f;
            if (out_loss) out_loss[0] = __fadd_rn(m, __fmul_rn(0.25f, m));
            g_loss_acc = 0.0f;    // restore state for next (graph-replayed) call
            __threadfence();
            g_ctr = 0u;
        }
    }
}

extern "C" void kernel_launch(void* const* d_in, const int* in_sizes, int n_in,
                              void* d_out, int out_size)
{
    const float* inp = nullptr;
    const float* wt  = nullptr;
    for (int i = 0; i < n_in; i++) {
        if (in_sizes[i] == 8388608) inp = (const float*)d_in[i];
        else if (in_sizes[i] == 65536) wt = (const float*)d_in[i];
    }
    if (!inp || !wt) return;

    float* out = (float*)d_out;
    const long long Q = 8388608LL, ENC = 134217728LL;
    long long os = (long long)out_size;

    float* oL = nullptr; float* oQ = nullptr; float* oE = nullptr;
    if (os == 1 + Q + ENC)      { oL = out; oQ = out + 1; oE = out + 1 + Q; }
    else if (os == Q + ENC)     { oQ = out; oE = out + Q; }
    else if (os == ENC)         { oE = out; }
    else if (os == Q)           { oQ = out; }
    else if (os == 1)           { oL = out; }
    else {
        oL = out;
        if (os >= 1 + Q) oQ = out + 1;
        if (os >= 1 + Q + ENC) oE = out + 1 + Q;
    }

    cudaFuncSetAttribute(vq_main_kernel,
                         cudaFuncAttributeMaxDynamicSharedMemorySize, SMEM_BYTES);

    vq_prep_kernel<<<(ECODES + 255) / 256, 256>>>(wt);
    vq_main_kernel<<<GRID, BLOCK, SMEM_BYTES>>>(inp, wt, oQ, oE, oL);
}